// round 15
// baseline (speedup 1.0000x reference)
#include <cuda_runtime.h>
#include <cuda_fp16.h>
#include <cstdint>
#include <math.h>

#define NB 32
#define NS 1024
#define NH 1024
#define ND 128

// persistent scratch (__device__ globals per allocation rules) — fp16
__device__ __half g_q[NB * NS * ND];
__device__ __half g_k[NB * NS * ND];
__device__ __half g_v[NB * NS * ND];
__device__ __half g_pe[NB * NS * NS];  // unnormalized exp(S), fp16
__device__ __half g_wt[3 * ND * NH];   // [w][n][k] transposed weights

// ---------------------------------------------------------------------------
// helpers
// ---------------------------------------------------------------------------
__device__ __forceinline__ uint32_t smem_u32(const void* p) {
    uint32_t a;
    asm("{ .reg .u64 t; cvta.to.shared.u64 t, %1; cvt.u32.u64 %0, t; }" : "=r"(a) : "l"(p));
    return a;
}
__device__ __forceinline__ void ldsm_x4(uint32_t* r, uint32_t addr) {
    asm volatile("ldmatrix.sync.aligned.m8n8.x4.shared.b16 {%0,%1,%2,%3}, [%4];"
                 : "=r"(r[0]), "=r"(r[1]), "=r"(r[2]), "=r"(r[3]) : "r"(addr));
}
__device__ __forceinline__ void ldsm_x4_t(uint32_t* r, uint32_t addr) {
    asm volatile("ldmatrix.sync.aligned.m8n8.x4.trans.shared.b16 {%0,%1,%2,%3}, [%4];"
                 : "=r"(r[0]), "=r"(r[1]), "=r"(r[2]), "=r"(r[3]) : "r"(addr));
}
__device__ __forceinline__ void mma16816(float* d, const uint32_t* a, const uint32_t* b) {
    asm volatile(
        "mma.sync.aligned.m16n8k16.row.col.f32.f16.f16.f32 "
        "{%0,%1,%2,%3}, {%4,%5,%6,%7}, {%8,%9}, {%0,%1,%2,%3};"
        : "+f"(d[0]), "+f"(d[1]), "+f"(d[2]), "+f"(d[3])
        : "r"(a[0]), "r"(a[1]), "r"(a[2]), "r"(a[3]), "r"(b[0]), "r"(b[1]));
}
__device__ __forceinline__ uint32_t pack_h2(float a, float b) {
    __half2 h = __floats2half2_rn(a, b);
    return *(uint32_t*)&h;
}
__device__ __forceinline__ float fast_exp(float x) {
    float t = x * 1.4426950408889634f;
    int ii = __float2int_rn(t);
    float f = t - (float)ii;
    float y = f * 0.6931471805599453f;
    float p = 1.0f + y * (1.0f + y * (0.5f + y * (0.16666667f + y * (0.041666668f + y * 0.008333334f))));
    return __int_as_float(__float_as_int(p) + (ii << 23));
}
__device__ __forceinline__ void cp_async16(uint32_t smem_addr, const void* gptr) {
    asm volatile("cp.async.cg.shared.global [%0], [%1], 16;" :: "r"(smem_addr), "l"(gptr));
}
#define CP_COMMIT() asm volatile("cp.async.commit_group;" ::: "memory")
#define CP_WAIT(n)  asm volatile("cp.async.wait_group %0;" :: "n"(n) : "memory")

// ---------------------------------------------------------------------------
// Weight transpose to fp16
// ---------------------------------------------------------------------------
__global__ __launch_bounds__(256) void convw_kernel(
    const float* __restrict__ Wq, const float* __restrict__ Wk, const float* __restrict__ Wv)
{
    __shared__ float sW[64 * 129];
    int w = blockIdx.x >> 4;
    int k0 = (blockIdx.x & 15) * 64;
    const float* W = (w == 0) ? Wq : (w == 1) ? Wk : Wv;
    int tid = threadIdx.x;

    #pragma unroll
    for (int it = 0; it < 32; it++) {
        int f = tid + it * 256;
        int kk = f >> 7, n = f & 127;
        sW[kk * 129 + n] = W[(size_t)(k0 + kk) * ND + n];
    }
    __syncthreads();

    #pragma unroll
    for (int it = 0; it < 32; it++) {
        int f = tid + it * 256;
        int n = f >> 6, kk = f & 63;
        g_wt[(size_t)w * ND * NH + (size_t)n * NH + k0 + kk] =
            __float2half_rn(sW[kk * 129 + n]);
    }
}

// ---------------------------------------------------------------------------
// QKV GEMM: BM=128 BN=128 BK=32, 128 threads (4 warps 2x2, warp 64x64).
// ---------------------------------------------------------------------------
#define FSTRIDE 36
#define BSTRIDE 40
#define QK_A   0                             // 128 x 36 fp32 = 18432 B
#define QK_B   18432                         // 128 x 40 fp16 = 10240 B
#define QK_STAGE 28672
#define QK_SMEM (2 * QK_STAGE)

__global__ __launch_bounds__(128, 2) void qkv_mma_kernel(
    const float* __restrict__ X,
    const float* __restrict__ bq, const float* __restrict__ bk, const float* __restrict__ bv)
{
    extern __shared__ char sm[];
    const uint32_t uS = smem_u32(sm);

    const int tid = threadIdx.x;
    const int wid = tid >> 5, lid = tid & 31;
    const int w  = blockIdx.x;
    const int m0 = blockIdx.y * 128;

    const __half* Wt = g_wt + (size_t)w * ND * NH;
    const float* bias = (w == 0) ? bq : (w == 1) ? bk : bv;
    __half* out = (w == 0) ? g_q : (w == 1) ? g_k : g_v;
    const float oscale = (w == 0) ? 0.08838834764831845f : 1.0f;

    const int warpM = (wid >> 1) * 64;
    const int warpN = (wid & 1) * 64;

    const int bx_row  = (lid & 7) + (lid >> 4) * 8;
    const int bx_koff = ((lid >> 3) & 1) * 8;
    const int p_row = lid >> 2;
    const int p_col = (lid & 3) * 2;

    float acc[4][8][4];
    #pragma unroll
    for (int i = 0; i < 4; i++)
        #pragma unroll
        for (int j = 0; j < 8; j++)
            #pragma unroll
            for (int c = 0; c < 4; c++) acc[i][j][c] = 0.f;

    auto issue_stage = [&](int kc, int s) {
        const int k0 = kc * 32;
        const uint32_t base = uS + s * QK_STAGE;
        #pragma unroll
        for (int it = 0; it < 8; it++) {
            int f = tid + it * 128;
            int row = f >> 3, u = f & 7;
            const float* src = X + (size_t)(m0 + row) * NH + k0 + u * 4;
            cp_async16(base + QK_A + (uint32_t)(row * FSTRIDE + u * 4) * 4, src);
        }
        #pragma unroll
        for (int it = 0; it < 4; it++) {
            int f = tid + it * 128;
            int row = f >> 2, u = f & 3;
            const __half* src = Wt + (size_t)row * NH + k0 + u * 8;
            cp_async16(base + QK_B + (uint32_t)(row * BSTRIDE + u * 8) * 2, src);
        }
        CP_COMMIT();
    };

    issue_stage(0, 0);

    for (int kc = 0; kc < 32; kc++) {
        if (kc < 31) { issue_stage(kc + 1, (kc + 1) & 1); CP_WAIT(1); }
        else         { CP_WAIT(0); }
        __syncthreads();

        const float* Ab = (const float*)(sm + (kc & 1) * QK_STAGE + QK_A);
        const uint32_t bb = uS + (kc & 1) * QK_STAGE;

        #pragma unroll
        for (int ks = 0; ks < 2; ks++) {
            uint32_t ah[4][4];
            #pragma unroll
            for (int mi = 0; mi < 4; mi++) {
                int row  = warpM + mi * 16 + p_row;
                int kcol = ks * 16 + p_col;
                float2 p0 = *(const float2*)&Ab[row * FSTRIDE + kcol];
                float2 p1 = *(const float2*)&Ab[(row + 8) * FSTRIDE + kcol];
                float2 p2 = *(const float2*)&Ab[row * FSTRIDE + kcol + 8];
                float2 p3 = *(const float2*)&Ab[(row + 8) * FSTRIDE + kcol + 8];
                ah[mi][0] = pack_h2(p0.x, p0.y);
                ah[mi][1] = pack_h2(p1.x, p1.y);
                ah[mi][2] = pack_h2(p2.x, p2.y);
                ah[mi][3] = pack_h2(p3.x, p3.y);
            }
            #pragma unroll
            for (int njp = 0; njp < 4; njp++) {
                uint32_t boff = ((warpN + njp * 16 + bx_row) * BSTRIDE + ks * 16 + bx_koff) * 2;
                uint32_t bh[4];
                ldsm_x4(bh, bb + QK_B + boff);
                #pragma unroll
                for (int h = 0; h < 2; h++)
                    #pragma unroll
                    for (int mi = 0; mi < 4; mi++)
                        mma16816(acc[mi][njp * 2 + h], ah[mi], &bh[h * 2]);
            }
        }
        __syncthreads();
    }

    #pragma unroll
    for (int mi = 0; mi < 4; mi++) {
        #pragma unroll
        for (int nj = 0; nj < 8; nj++) {
            int r0 = m0 + warpM + mi * 16 + (lid >> 2);
            int c0 = warpN + nj * 8 + (lid & 3) * 2;
            float b0 = bias[c0], b1 = bias[c0 + 1];
            uint32_t h01 = pack_h2((acc[mi][nj][0] + b0) * oscale, (acc[mi][nj][1] + b1) * oscale);
            uint32_t h23 = pack_h2((acc[mi][nj][2] + b0) * oscale, (acc[mi][nj][3] + b1) * oscale);
            *(uint32_t*)&out[(size_t)r0 * ND + c0] = h01;
            *(uint32_t*)&out[(size_t)(r0 + 8) * ND + c0] = h23;
        }
    }
}

// ---------------------------------------------------------------------------
// Fused attention: per CTA = 64 queries x full 1024 keys, batch b.
// 128 threads = 4 warps, warp owns 16 query rows.
// Loop over 16 chunks of 64 keys: S-MMA -> exp (regs) -> P frags (regs)
// -> PV-MMA accumulate; expS fp16 streamed to g_pe; sums finalized in-CTA;
// epilogue writes O and normalized fp32 probs (re-reading L2-hot g_pe).
// ---------------------------------------------------------------------------
#define ASTR 136                              // smem stride (halves)
#define AT_Q 0                                // 64 x 136 fp16 = 17408 B
#define AT_K 17408
#define AT_V (17408 + 17408)
#define KV_STAGE (2 * 17408)
#define AT_SMEM (17408 + 2 * KV_STAGE)        // 87040 B

__global__ __launch_bounds__(128, 2) void attn_kernel(float* __restrict__ probs,
                                                      float* __restrict__ o_out)
{
    extern __shared__ char sm[];
    __shared__ float s_inv[64];
    const uint32_t uS = smem_u32(sm);

    const int tid = threadIdx.x;
    const int wid = tid >> 5, lid = tid & 31;
    const int m0 = blockIdx.x * 64;
    const int b  = blockIdx.y;
    const size_t qbase  = (size_t)(b * NS + m0) * ND;
    const size_t kvbase = (size_t)(b * NS) * ND;

    const int a_row  = lid & 15;
    const int a_koff = (lid >> 4) * 8;
    const int bx_row  = (lid & 7) + (lid >> 4) * 8;
    const int bx_koff = ((lid >> 3) & 1) * 8;
    const int t_krow = (lid & 7) + ((lid >> 3) & 1) * 8;
    const int t_ncol = (lid >> 4) * 8;
    const int r  = lid >> 2;          // 0..7
    const int q2 = (lid & 3) * 2;     // 0,2,4,6

    // ---- stage Q (group 0) ----
    #pragma unroll
    for (int it = 0; it < 8; it++) {
        int f = tid + it * 128;
        int row = f >> 4, u = f & 15;
        cp_async16(uS + AT_Q + (uint32_t)(row * ASTR + u * 8) * 2,
                   g_q + qbase + (size_t)row * ND + u * 8);
    }
    CP_COMMIT();

    auto stage_kv = [&](int c, int s) {
        const uint32_t kb = uS + AT_K + s * KV_STAGE;
        const uint32_t vb = uS + AT_V + s * KV_STAGE;
        const size_t gk = kvbase + (size_t)(c * 64) * ND;
        #pragma unroll
        for (int it = 0; it < 8; it++) {
            int f = tid + it * 128;
            int row = f >> 4, u = f & 15;
            cp_async16(kb + (uint32_t)(row * ASTR + u * 8) * 2,
                       g_k + gk + (size_t)row * ND + u * 8);
        }
        #pragma unroll
        for (int it = 0; it < 8; it++) {
            int f = tid + it * 128;
            int row = f >> 4, u = f & 15;
            cp_async16(vb + (uint32_t)(row * ASTR + u * 8) * 2,
                       g_v + gk + (size_t)row * ND + u * 8);
        }
        CP_COMMIT();
    };

    stage_kv(0, 0);
    CP_WAIT(1);          // Q ready
    __syncthreads();

    // ---- Q fragments, register resident for the whole kernel ----
    uint32_t qf[8][4];
    #pragma unroll
    for (int ks = 0; ks < 8; ks++)
        ldsm_x4(qf[ks], uS + AT_Q + (uint32_t)((wid * 16 + a_row) * ASTR + ks * 16 + a_koff) * 2);

    float oacc[16][4];
    #pragma unroll
    for (int nt = 0; nt < 16; nt++)
        #pragma unroll
        for (int c = 0; c < 4; c++) oacc[nt][c] = 0.f;
    float rowsum0 = 0.f, rowsum1 = 0.f;

    const size_t perow0 = (size_t)(b * NS + m0 + wid * 16 + r) * NS;
    const size_t perow1 = perow0 + (size_t)8 * NS;

    for (int c = 0; c < 16; c++) {
        if (c < 15) { stage_kv(c + 1, (c + 1) & 1); CP_WAIT(1); }
        else        { CP_WAIT(0); }
        __syncthreads();

        const uint32_t kb = uS + AT_K + (c & 1) * KV_STAGE;
        const uint32_t vb = uS + AT_V + (c & 1) * KV_STAGE;

        // ---- S = Q @ K^T for this 64-key chunk ----
        float sacc[8][4];
        #pragma unroll
        for (int nt = 0; nt < 8; nt++)
            #pragma unroll
            for (int cc = 0; cc < 4; cc++) sacc[nt][cc] = 0.f;

        #pragma unroll
        for (int ks = 0; ks < 8; ks++) {
            #pragma unroll
            for (int np = 0; np < 4; np++) {
                uint32_t bh[4];
                ldsm_x4(bh, kb + (uint32_t)((np * 16 + bx_row) * ASTR + ks * 16 + bx_koff) * 2);
                mma16816(sacc[np * 2],     qf[ks], &bh[0]);
                mma16816(sacc[np * 2 + 1], qf[ks], &bh[2]);
            }
        }

        // ---- exp, expS store, row sums, P fragments (in registers) ----
        uint32_t pf[4][4];
        #pragma unroll
        for (int j = 0; j < 4; j++) {
            float e00 = fast_exp(sacc[2 * j][0]),     e01 = fast_exp(sacc[2 * j][1]);
            float e02 = fast_exp(sacc[2 * j][2]),     e03 = fast_exp(sacc[2 * j][3]);
            float e10 = fast_exp(sacc[2 * j + 1][0]), e11 = fast_exp(sacc[2 * j + 1][1]);
            float e12 = fast_exp(sacc[2 * j + 1][2]), e13 = fast_exp(sacc[2 * j + 1][3]);
            pf[j][0] = pack_h2(e00, e01);   // (r,   k16j+q2)
            pf[j][1] = pack_h2(e02, e03);   // (r+8, k16j+q2)
            pf[j][2] = pack_h2(e10, e11);   // (r,   k16j+8+q2)
            pf[j][3] = pack_h2(e12, e13);   // (r+8, k16j+8+q2)
            rowsum0 += (e00 + e01) + (e10 + e11);
            rowsum1 += (e02 + e03) + (e12 + e13);
            size_t col = (size_t)(c * 64 + j * 16 + q2);
            *(uint32_t*)&g_pe[perow0 + col]     = pf[j][0];
            *(uint32_t*)&g_pe[perow0 + col + 8] = pf[j][2];
            *(uint32_t*)&g_pe[perow1 + col]     = pf[j][1];
            *(uint32_t*)&g_pe[perow1 + col + 8] = pf[j][3];
        }

        // ---- O += P @ V ----
        #pragma unroll
        for (int j = 0; j < 4; j++) {
            #pragma unroll
            for (int np = 0; np < 8; np++) {
                uint32_t vh[4];
                ldsm_x4_t(vh, vb + (uint32_t)((j * 16 + t_krow) * ASTR + np * 16 + t_ncol) * 2);
                mma16816(oacc[np * 2],     pf[j], &vh[0]);
                mma16816(oacc[np * 2 + 1], pf[j], &vh[2]);
            }
        }
        __syncthreads();
    }

    // ---- finalize sums ----
    rowsum0 += __shfl_xor_sync(0xffffffffu, rowsum0, 1);
    rowsum0 += __shfl_xor_sync(0xffffffffu, rowsum0, 2);
    rowsum1 += __shfl_xor_sync(0xffffffffu, rowsum1, 1);
    rowsum1 += __shfl_xor_sync(0xffffffffu, rowsum1, 2);
    const float inv0 = 1.f / rowsum0;
    const float inv1 = 1.f / rowsum1;
    if ((lid & 3) == 0) {
        s_inv[wid * 16 + r]     = inv0;
        s_inv[wid * 16 + r + 8] = inv1;
    }
    __syncwarp();

    // ---- O epilogue ----
    {
        int r0 = m0 + wid * 16 + r;
        #pragma unroll
        for (int nt = 0; nt < 16; nt++) {
            int c0 = nt * 8 + q2;
            *(float2*)&o_out[((size_t)(b * NS) + r0) * ND + c0] =
                make_float2(oacc[nt][0] * inv0, oacc[nt][1] * inv0);
            *(float2*)&o_out[((size_t)(b * NS) + r0 + 8) * ND + c0] =
                make_float2(oacc[nt][2] * inv1, oacc[nt][3] * inv1);
        }
    }

    // ---- probs epilogue: normalize expS (L2-hot) -> fp32 probs ----
    {
        const size_t pwbase = (size_t)(b * NS + m0 + wid * 16) * NS;
        #pragma unroll 4
        for (int it = 0; it < 64; it++) {
            int idx = it * 32 + lid;          // uint4 index within warp's 16 rows
            int rowl = idx >> 7;              // 128 uint4 per row
            int col  = (idx & 127) * 8;
            float iv = s_inv[wid * 16 + rowl];
            uint4 raw = *(const uint4*)&g_pe[pwbase + (size_t)rowl * NS + col];
            float2 a0 = __half22float2(*(__half2*)&raw.x);
            float2 a1 = __half22float2(*(__half2*)&raw.y);
            float2 a2 = __half22float2(*(__half2*)&raw.z);
            float2 a3 = __half22float2(*(__half2*)&raw.w);
            float4 o0 = make_float4(a0.x * iv, a0.y * iv, a1.x * iv, a1.y * iv);
            float4 o1 = make_float4(a2.x * iv, a2.y * iv, a3.x * iv, a3.y * iv);
            *(float4*)&probs[pwbase + (size_t)rowl * NS + col]     = o0;
            *(float4*)&probs[pwbase + (size_t)rowl * NS + col + 4] = o1;
        }
    }
}

// ---------------------------------------------------------------------------
extern "C" void kernel_launch(void* const* d_in, const int* in_sizes, int n_in,
                              void* d_out, int out_size)
{
    const float* X  = (const float*)d_in[0];
    const float* Wq = (const float*)d_in[1];
    const float* bq = (const float*)d_in[2];
    const float* Wk = (const float*)d_in[3];
    const float* bk = (const float*)d_in[4];
    const float* Wv = (const float*)d_in[5];
    const float* bv = (const float*)d_in[6];

    float* out   = (float*)d_out;                 // [32,1024,128]
    float* probs = out + (size_t)NB * NS * ND;    // [32,1024,1024]

    cudaFuncSetAttribute(qkv_mma_kernel, cudaFuncAttributeMaxDynamicSharedMemorySize, QK_SMEM);
    cudaFuncSetAttribute(attn_kernel, cudaFuncAttributeMaxDynamicSharedMemorySize, AT_SMEM);

    convw_kernel<<<48, 256>>>(Wq, Wk, Wv);
    qkv_mma_kernel<<<dim3(3, 256), 128, QK_SMEM>>>(X, bq, bk, bv);
    attn_kernel<<<dim3(16, 32), 128, AT_SMEM>>>(probs, out);
}

// round 16
// speedup vs baseline: 1.0339x; 1.0339x over previous
#include <cuda_runtime.h>
#include <cuda_fp16.h>
#include <cstdint>
#include <math.h>

#define NB 32
#define NS 1024
#define NH 1024
#define ND 128

// persistent scratch (__device__ globals per allocation rules) — fp16
__device__ __half g_q[NB * NS * ND];
__device__ __half g_k[NB * NS * ND];
__device__ __half g_v[NB * NS * ND];
__device__ __half g_pe[NB * NS * NS];  // unnormalized exp(S), fp16
__device__ __half g_wt[3 * ND * NH];   // [w][n][k] transposed weights
__device__ float  g_sums[NB * NS];     // per-row exp sums (atomic)

// ---------------------------------------------------------------------------
// helpers
// ---------------------------------------------------------------------------
__device__ __forceinline__ uint32_t smem_u32(const void* p) {
    uint32_t a;
    asm("{ .reg .u64 t; cvta.to.shared.u64 t, %1; cvt.u32.u64 %0, t; }" : "=r"(a) : "l"(p));
    return a;
}
__device__ __forceinline__ void ldsm_x4(uint32_t* r, uint32_t addr) {
    asm volatile("ldmatrix.sync.aligned.m8n8.x4.shared.b16 {%0,%1,%2,%3}, [%4];"
                 : "=r"(r[0]), "=r"(r[1]), "=r"(r[2]), "=r"(r[3]) : "r"(addr));
}
__device__ __forceinline__ void ldsm_x4_t(uint32_t* r, uint32_t addr) {
    asm volatile("ldmatrix.sync.aligned.m8n8.x4.trans.shared.b16 {%0,%1,%2,%3}, [%4];"
                 : "=r"(r[0]), "=r"(r[1]), "=r"(r[2]), "=r"(r[3]) : "r"(addr));
}
__device__ __forceinline__ void mma16816(float* d, const uint32_t* a, const uint32_t* b) {
    asm volatile(
        "mma.sync.aligned.m16n8k16.row.col.f32.f16.f16.f32 "
        "{%0,%1,%2,%3}, {%4,%5,%6,%7}, {%8,%9}, {%0,%1,%2,%3};"
        : "+f"(d[0]), "+f"(d[1]), "+f"(d[2]), "+f"(d[3])
        : "r"(a[0]), "r"(a[1]), "r"(a[2]), "r"(a[3]), "r"(b[0]), "r"(b[1]));
}
__device__ __forceinline__ uint32_t pack_h2(float a, float b) {
    __half2 h = __floats2half2_rn(a, b);
    return *(uint32_t*)&h;
}
__device__ __forceinline__ float fast_exp(float x) {
    float t = x * 1.4426950408889634f;
    int ii = __float2int_rn(t);
    float f = t - (float)ii;
    float y = f * 0.6931471805599453f;
    float p = 1.0f + y * (1.0f + y * (0.5f + y * (0.16666667f + y * (0.041666668f + y * 0.008333334f))));
    return __int_as_float(__float_as_int(p) + (ii << 23));
}
__device__ __forceinline__ void cp_async16(uint32_t smem_addr, const void* gptr) {
    asm volatile("cp.async.cg.shared.global [%0], [%1], 16;" :: "r"(smem_addr), "l"(gptr));
}
#define CP_COMMIT() asm volatile("cp.async.commit_group;" ::: "memory")
#define CP_WAIT(n)  asm volatile("cp.async.wait_group %0;" :: "n"(n) : "memory")

// ---------------------------------------------------------------------------
// Weight transpose to fp16 + zero g_sums (runs every replay)
// ---------------------------------------------------------------------------
__global__ __launch_bounds__(256) void convw_kernel(
    const float* __restrict__ Wq, const float* __restrict__ Wk, const float* __restrict__ Wv)
{
    __shared__ float sW[64 * 129];
    int w = blockIdx.x >> 4;
    int k0 = (blockIdx.x & 15) * 64;
    const float* W = (w == 0) ? Wq : (w == 1) ? Wk : Wv;
    int tid = threadIdx.x;

    for (int i = blockIdx.x * 256 + tid; i < NB * NS; i += gridDim.x * 256)
        g_sums[i] = 0.f;

    #pragma unroll
    for (int it = 0; it < 32; it++) {
        int f = tid + it * 256;
        int kk = f >> 7, n = f & 127;
        sW[kk * 129 + n] = W[(size_t)(k0 + kk) * ND + n];
    }
    __syncthreads();

    #pragma unroll
    for (int it = 0; it < 32; it++) {
        int f = tid + it * 256;
        int n = f >> 6, kk = f & 63;
        g_wt[(size_t)w * ND * NH + (size_t)n * NH + k0 + kk] =
            __float2half_rn(sW[kk * 129 + n]);
    }
}

// ---------------------------------------------------------------------------
// QKV GEMM: BM=128 BN=128 BK=32, 128 threads (4 warps 2x2, warp 64x64).
// ---------------------------------------------------------------------------
#define FSTRIDE 36
#define BSTRIDE 40
#define QK_A   0                             // 128 x 36 fp32 = 18432 B
#define QK_B   18432                         // 128 x 40 fp16 = 10240 B
#define QK_STAGE 28672
#define QK_SMEM (2 * QK_STAGE)

__global__ __launch_bounds__(128, 2) void qkv_mma_kernel(
    const float* __restrict__ X,
    const float* __restrict__ bq, const float* __restrict__ bk, const float* __restrict__ bv)
{
    extern __shared__ char sm[];
    const uint32_t uS = smem_u32(sm);

    const int tid = threadIdx.x;
    const int wid = tid >> 5, lid = tid & 31;
    const int w  = blockIdx.x;
    const int m0 = blockIdx.y * 128;

    const __half* Wt = g_wt + (size_t)w * ND * NH;
    const float* bias = (w == 0) ? bq : (w == 1) ? bk : bv;
    __half* out = (w == 0) ? g_q : (w == 1) ? g_k : g_v;
    const float oscale = (w == 0) ? 0.08838834764831845f : 1.0f;

    const int warpM = (wid >> 1) * 64;
    const int warpN = (wid & 1) * 64;

    const int bx_row  = (lid & 7) + (lid >> 4) * 8;
    const int bx_koff = ((lid >> 3) & 1) * 8;
    const int p_row = lid >> 2;
    const int p_col = (lid & 3) * 2;

    float acc[4][8][4];
    #pragma unroll
    for (int i = 0; i < 4; i++)
        #pragma unroll
        for (int j = 0; j < 8; j++)
            #pragma unroll
            for (int c = 0; c < 4; c++) acc[i][j][c] = 0.f;

    auto issue_stage = [&](int kc, int s) {
        const int k0 = kc * 32;
        const uint32_t base = uS + s * QK_STAGE;
        #pragma unroll
        for (int it = 0; it < 8; it++) {
            int f = tid + it * 128;
            int row = f >> 3, u = f & 7;
            const float* src = X + (size_t)(m0 + row) * NH + k0 + u * 4;
            cp_async16(base + QK_A + (uint32_t)(row * FSTRIDE + u * 4) * 4, src);
        }
        #pragma unroll
        for (int it = 0; it < 4; it++) {
            int f = tid + it * 128;
            int row = f >> 2, u = f & 3;
            const __half* src = Wt + (size_t)row * NH + k0 + u * 8;
            cp_async16(base + QK_B + (uint32_t)(row * BSTRIDE + u * 8) * 2, src);
        }
        CP_COMMIT();
    };

    issue_stage(0, 0);

    for (int kc = 0; kc < 32; kc++) {
        if (kc < 31) { issue_stage(kc + 1, (kc + 1) & 1); CP_WAIT(1); }
        else         { CP_WAIT(0); }
        __syncthreads();

        const float* Ab = (const float*)(sm + (kc & 1) * QK_STAGE + QK_A);
        const uint32_t bb = uS + (kc & 1) * QK_STAGE;

        #pragma unroll
        for (int ks = 0; ks < 2; ks++) {
            uint32_t ah[4][4];
            #pragma unroll
            for (int mi = 0; mi < 4; mi++) {
                int row  = warpM + mi * 16 + p_row;
                int kcol = ks * 16 + p_col;
                float2 p0 = *(const float2*)&Ab[row * FSTRIDE + kcol];
                float2 p1 = *(const float2*)&Ab[(row + 8) * FSTRIDE + kcol];
                float2 p2 = *(const float2*)&Ab[row * FSTRIDE + kcol + 8];
                float2 p3 = *(const float2*)&Ab[(row + 8) * FSTRIDE + kcol + 8];
                ah[mi][0] = pack_h2(p0.x, p0.y);
                ah[mi][1] = pack_h2(p1.x, p1.y);
                ah[mi][2] = pack_h2(p2.x, p2.y);
                ah[mi][3] = pack_h2(p3.x, p3.y);
            }
            #pragma unroll
            for (int njp = 0; njp < 4; njp++) {
                uint32_t boff = ((warpN + njp * 16 + bx_row) * BSTRIDE + ks * 16 + bx_koff) * 2;
                uint32_t bh[4];
                ldsm_x4(bh, bb + QK_B + boff);
                #pragma unroll
                for (int h = 0; h < 2; h++)
                    #pragma unroll
                    for (int mi = 0; mi < 4; mi++)
                        mma16816(acc[mi][njp * 2 + h], ah[mi], &bh[h * 2]);
            }
        }
        __syncthreads();
    }

    #pragma unroll
    for (int mi = 0; mi < 4; mi++) {
        #pragma unroll
        for (int nj = 0; nj < 8; nj++) {
            int r0 = m0 + warpM + mi * 16 + (lid >> 2);
            int c0 = warpN + nj * 8 + (lid & 3) * 2;
            float b0 = bias[c0], b1 = bias[c0 + 1];
            uint32_t h01 = pack_h2((acc[mi][nj][0] + b0) * oscale, (acc[mi][nj][1] + b1) * oscale);
            uint32_t h23 = pack_h2((acc[mi][nj][2] + b0) * oscale, (acc[mi][nj][3] + b1) * oscale);
            *(uint32_t*)&out[(size_t)r0 * ND + c0] = h01;
            *(uint32_t*)&out[(size_t)(r0 + 8) * ND + c0] = h23;
        }
    }
}

// ---------------------------------------------------------------------------
// score_kernel: writes exp(S) fp16 (unnormalized) + atomic per-row exp-sums.
// 128 threads, 4 warps 2x2, warp 64x64.
// ---------------------------------------------------------------------------
#define SC_Q 0
#define SC_K 10240
#define SC_STAGE 20480
#define SC_SMEM (2 * SC_STAGE)

__global__ __launch_bounds__(128, 2) void score_kernel()
{
    extern __shared__ char sm[];
    const uint32_t uS = smem_u32(sm);

    const int tid = threadIdx.x;
    const int wid = tid >> 5, lid = tid & 31;
    const int m0 = blockIdx.x * 128;
    const int n0 = blockIdx.y * 128;
    const int b  = blockIdx.z;
    const size_t qbase = (size_t)(b * NS + m0) * ND;
    const size_t kbase = (size_t)(b * NS + n0) * ND;

    const int warpM = (wid >> 1) * 64;
    const int warpN = (wid & 1) * 64;
    const int a_row  = lid & 15;
    const int a_koff = (lid >> 4) * 8;
    const int bx_row  = (lid & 7) + (lid >> 4) * 8;
    const int bx_koff = ((lid >> 3) & 1) * 8;

    float acc[4][8][4];
    #pragma unroll
    for (int i = 0; i < 4; i++)
        #pragma unroll
        for (int j = 0; j < 8; j++)
            #pragma unroll
            for (int c = 0; c < 4; c++) acc[i][j][c] = 0.f;

    auto issue_stage = [&](int kc, int s) {
        const int k0 = kc * 32;
        const uint32_t base = uS + s * SC_STAGE;
        #pragma unroll
        for (int it = 0; it < 8; it++) {
            int f = tid + it * 128;
            int arr = f >> 9;
            int g = f & 511;
            int row = g >> 2, u = g & 3;
            const __half* src = (arr ? g_k + kbase : g_q + qbase) + (size_t)row * ND + k0 + u * 8;
            cp_async16(base + (arr ? SC_K : SC_Q) + (uint32_t)(row * BSTRIDE + u * 8) * 2, src);
        }
        CP_COMMIT();
    };

    issue_stage(0, 0);

    for (int kc = 0; kc < 4; kc++) {
        if (kc < 3) { issue_stage(kc + 1, (kc + 1) & 1); CP_WAIT(1); }
        else        { CP_WAIT(0); }
        __syncthreads();

        const uint32_t base = uS + (kc & 1) * SC_STAGE;
        #pragma unroll
        for (int ks = 0; ks < 2; ks++) {
            uint32_t ah[4][4];
            #pragma unroll
            for (int mi = 0; mi < 4; mi++) {
                uint32_t off = ((warpM + mi * 16 + a_row) * BSTRIDE + ks * 16 + a_koff) * 2;
                ldsm_x4(ah[mi], base + SC_Q + off);
            }
            #pragma unroll
            for (int njp = 0; njp < 4; njp++) {
                uint32_t boff = ((warpN + njp * 16 + bx_row) * BSTRIDE + ks * 16 + bx_koff) * 2;
                uint32_t bh[4];
                ldsm_x4(bh, base + SC_K + boff);
                #pragma unroll
                for (int h = 0; h < 2; h++)
                    #pragma unroll
                    for (int mi = 0; mi < 4; mi++)
                        mma16816(acc[mi][njp * 2 + h], ah[mi], &bh[h * 2]);
            }
        }
        __syncthreads();
    }

    // epilogue: exp -> fp16 scratch + row sums (shfl + atomic)
    __half* pe = g_pe + (size_t)b * NS * NS;
    #pragma unroll
    for (int mi = 0; mi < 4; mi++) {
        int r0 = m0 + warpM + mi * 16 + (lid >> 2);
        float rs0 = 0.f, rs1 = 0.f;
        #pragma unroll
        for (int nj = 0; nj < 8; nj++) {
            int c0 = n0 + warpN + nj * 8 + (lid & 3) * 2;
            float e0 = fast_exp(acc[mi][nj][0]);
            float e1 = fast_exp(acc[mi][nj][1]);
            float e2 = fast_exp(acc[mi][nj][2]);
            float e3 = fast_exp(acc[mi][nj][3]);
            *(uint32_t*)&pe[(size_t)r0 * NS + c0]       = pack_h2(e0, e1);
            *(uint32_t*)&pe[(size_t)(r0 + 8) * NS + c0] = pack_h2(e2, e3);
            rs0 += e0 + e1;
            rs1 += e2 + e3;
        }
        rs0 += __shfl_xor_sync(0xffffffffu, rs0, 1);
        rs0 += __shfl_xor_sync(0xffffffffu, rs0, 2);
        rs1 += __shfl_xor_sync(0xffffffffu, rs1, 1);
        rs1 += __shfl_xor_sync(0xffffffffu, rs1, 2);
        if ((lid & 3) == 0) {
            atomicAdd(&g_sums[b * NS + r0], rs0);
            atomicAdd(&g_sums[b * NS + r0 + 8], rs1);
        }
    }
}

// ---------------------------------------------------------------------------
// pv_kernel: O = (expS_fp16 @ V) * inv_sum.
// BM=64, grid(16,32)=512, 128 threads (4 warps 2x2, warp 32x64), 4 CTAs/SM.
// Mainloop is pure cp.async/ldsm/MMA; normalized fp32 probs written in a
// streaming epilogue from g_pe (L2-resident) via LDG -> STG.
// ---------------------------------------------------------------------------
#define PV_P   0                             // 64 x 40 fp16 = 5120 B
#define PV_V   5120                          // 32 x 136 fp16 = 8704 B
#define PV_STAGE 13824
#define PV_SMEM (2 * PV_STAGE)
#define VSTRIDE 136

__global__ __launch_bounds__(128, 4) void pv_kernel(float* __restrict__ probs,
                                                    float* __restrict__ o_out)
{
    extern __shared__ char sm[];
    __shared__ float s_inv[64];
    const uint32_t uS = smem_u32(sm);

    const int tid = threadIdx.x;
    const int wid = tid >> 5, lid = tid & 31;
    const int m0 = blockIdx.x * 64;
    const int b  = blockIdx.y;
    const size_t pbase = (size_t)(b * NS + m0) * NS;
    const size_t vbase = (size_t)(b * NS) * ND;

    const int warpM = (wid >> 1) * 32;       // 0, 32
    const int warpN = (wid & 1) * 64;        // 0, 64
    const int a_row  = lid & 15;
    const int a_koff = (lid >> 4) * 8;
    const int t_krow = (lid & 7) + ((lid >> 3) & 1) * 8;
    const int t_ncol = (lid >> 4) * 8;
    const int p_row = lid >> 2;

    if (tid < 64) s_inv[tid] = 1.0f / g_sums[b * NS + m0 + tid];

    float acc[2][8][4];
    #pragma unroll
    for (int i = 0; i < 2; i++)
        #pragma unroll
        for (int j = 0; j < 8; j++)
            #pragma unroll
            for (int c = 0; c < 4; c++) acc[i][j][c] = 0.f;

    auto issue_stage = [&](int kc, int s) {
        const int k0 = kc * 32;
        const uint32_t base = uS + s * PV_STAGE;
        // P: 64 rows x 32 fp16 = 256 cp16
        #pragma unroll
        for (int it = 0; it < 2; it++) {
            int f = tid + it * 128;
            int row = f >> 2, u = f & 3;
            const __half* src = g_pe + pbase + (size_t)row * NS + k0 + u * 8;
            cp_async16(base + PV_P + (uint32_t)(row * BSTRIDE + u * 8) * 2, src);
        }
        // V: 32 rows x 128 fp16 = 512 cp16
        #pragma unroll
        for (int it = 0; it < 4; it++) {
            int f = tid + it * 128;
            int row = f >> 4, u = f & 15;
            const __half* src = g_v + vbase + (size_t)(k0 + row) * ND + u * 8;
            cp_async16(base + PV_V + (uint32_t)(row * VSTRIDE + u * 8) * 2, src);
        }
        CP_COMMIT();
    };

    issue_stage(0, 0);
    __syncthreads();   // s_inv visible

    float inv0[2], inv1[2];
    #pragma unroll
    for (int mi = 0; mi < 2; mi++) {
        inv0[mi] = s_inv[warpM + mi * 16 + p_row];
        inv1[mi] = s_inv[warpM + mi * 16 + p_row + 8];
    }

    for (int kc = 0; kc < 32; kc++) {
        if (kc < 31) { issue_stage(kc + 1, (kc + 1) & 1); CP_WAIT(1); }
        else         { CP_WAIT(0); }
        __syncthreads();

        const uint32_t pb = uS + (kc & 1) * PV_STAGE;

        #pragma unroll
        for (int ks = 0; ks < 2; ks++) {
            uint32_t ph[2][4];
            #pragma unroll
            for (int mi = 0; mi < 2; mi++) {
                uint32_t off = ((warpM + mi * 16 + a_row) * BSTRIDE + ks * 16 + a_koff) * 2;
                ldsm_x4(ph[mi], pb + PV_P + off);
            }
            #pragma unroll
            for (int njp = 0; njp < 4; njp++) {
                uint32_t toff = (uint32_t)((ks * 16 + t_krow) * VSTRIDE + warpN + njp * 16 + t_ncol) * 2;
                uint32_t vh[4];
                ldsm_x4_t(vh, pb + PV_V + toff);
                #pragma unroll
                for (int h = 0; h < 2; h++)
                    #pragma unroll
                    for (int mi = 0; mi < 2; mi++)
                        mma16816(acc[mi][njp * 2 + h], ph[mi], &vh[h * 2]);
            }
        }
        __syncthreads();
    }

    // ---- O epilogue ----
    #pragma unroll
    for (int mi = 0; mi < 2; mi++) {
        #pragma unroll
        for (int nj = 0; nj < 8; nj++) {
            int r0 = m0 + warpM + mi * 16 + (lid >> 2);
            int c0 = warpN + nj * 8 + (lid & 3) * 2;
            *(float2*)&o_out[((size_t)(b * NS) + r0) * ND + c0] =
                make_float2(acc[mi][nj][0] * inv0[mi], acc[mi][nj][1] * inv0[mi]);
            *(float2*)&o_out[((size_t)(b * NS) + r0 + 8) * ND + c0] =
                make_float2(acc[mi][nj][2] * inv1[mi], acc[mi][nj][3] * inv1[mi]);
        }
    }

    // ---- probs epilogue: normalize g_pe (L2-hot LDG) -> fp32 probs ----
    {
        // 64 rows x 1024 cols = 8192 uint4; 128 threads -> 64 iterations
        #pragma unroll 4
        for (int it = 0; it < 64; it++) {
            int idx = it * 128 + tid;
            int rowl = idx >> 7;              // 128 uint4 per row
            int col  = (idx & 127) * 8;
            float iv = s_inv[rowl];
            uint4 raw = *(const uint4*)&g_pe[pbase + (size_t)rowl * NS + col];
            float2 a0 = __half22float2(*(__half2*)&raw.x);
            float2 a1 = __half22float2(*(__half2*)&raw.y);
            float2 a2 = __half22float2(*(__half2*)&raw.z);
            float2 a3 = __half22float2(*(__half2*)&raw.w);
            float4 o0 = make_float4(a0.x * iv, a0.y * iv, a1.x * iv, a1.y * iv);
            float4 o1 = make_float4(a2.x * iv, a2.y * iv, a3.x * iv, a3.y * iv);
            *(float4*)&probs[pbase + (size_t)rowl * NS + col]     = o0;
            *(float4*)&probs[pbase + (size_t)rowl * NS + col + 4] = o1;
        }
    }
}

// ---------------------------------------------------------------------------
extern "C" void kernel_launch(void* const* d_in, const int* in_sizes, int n_in,
                              void* d_out, int out_size)
{
    const float* X  = (const float*)d_in[0];
    const float* Wq = (const float*)d_in[1];
    const float* bq = (const float*)d_in[2];
    const float* Wk = (const float*)d_in[3];
    const float* bk = (const float*)d_in[4];
    const float* Wv = (const float*)d_in[5];
    const float* bv = (const float*)d_in[6];

    float* out   = (float*)d_out;                 // [32,1024,128]
    float* probs = out + (size_t)NB * NS * ND;    // [32,1024,1024]

    cudaFuncSetAttribute(qkv_mma_kernel, cudaFuncAttributeMaxDynamicSharedMemorySize, QK_SMEM);
    cudaFuncSetAttribute(score_kernel, cudaFuncAttributeMaxDynamicSharedMemorySize, SC_SMEM);
    cudaFuncSetAttribute(pv_kernel, cudaFuncAttributeMaxDynamicSharedMemorySize, PV_SMEM);

    convw_kernel<<<48, 256>>>(Wq, Wk, Wv);
    qkv_mma_kernel<<<dim3(3, 256), 128, QK_SMEM>>>(X, bq, bk, bv);
    score_kernel<<<dim3(8, 8, 32), 128, SC_SMEM>>>();
    pv_kernel<<<dim3(16, 32), 128, PV_SMEM>>>(probs, out);
}

// round 17
// speedup vs baseline: 1.1292x; 1.0922x over previous
#include <cuda_runtime.h>
#include <cuda_fp16.h>
#include <cstdint>
#include <math.h>

#define NB 32
#define NS 1024
#define NH 1024
#define ND 128

// persistent scratch (__device__ globals per allocation rules) — fp16
__device__ __half g_q[NB * NS * ND];
__device__ __half g_k[NB * NS * ND];
__device__ __half g_v[NB * NS * ND];
__device__ __half g_pe[NB * NS * NS];  // unnormalized exp(S), fp16
__device__ __half g_wt[3 * ND * NH];   // [w][n][k] transposed weights
__device__ float  g_sums[NB * NS];     // per-row exp sums (atomic)

// ---------------------------------------------------------------------------
// helpers
// ---------------------------------------------------------------------------
__device__ __forceinline__ uint32_t smem_u32(const void* p) {
    uint32_t a;
    asm("{ .reg .u64 t; cvta.to.shared.u64 t, %1; cvt.u32.u64 %0, t; }" : "=r"(a) : "l"(p));
    return a;
}
__device__ __forceinline__ void ldsm_x4(uint32_t* r, uint32_t addr) {
    asm volatile("ldmatrix.sync.aligned.m8n8.x4.shared.b16 {%0,%1,%2,%3}, [%4];"
                 : "=r"(r[0]), "=r"(r[1]), "=r"(r[2]), "=r"(r[3]) : "r"(addr));
}
__device__ __forceinline__ void ldsm_x4_t(uint32_t* r, uint32_t addr) {
    asm volatile("ldmatrix.sync.aligned.m8n8.x4.trans.shared.b16 {%0,%1,%2,%3}, [%4];"
                 : "=r"(r[0]), "=r"(r[1]), "=r"(r[2]), "=r"(r[3]) : "r"(addr));
}
__device__ __forceinline__ void mma16816(float* d, const uint32_t* a, const uint32_t* b) {
    asm volatile(
        "mma.sync.aligned.m16n8k16.row.col.f32.f16.f16.f32 "
        "{%0,%1,%2,%3}, {%4,%5,%6,%7}, {%8,%9}, {%0,%1,%2,%3};"
        : "+f"(d[0]), "+f"(d[1]), "+f"(d[2]), "+f"(d[3])
        : "r"(a[0]), "r"(a[1]), "r"(a[2]), "r"(a[3]), "r"(b[0]), "r"(b[1]));
}
__device__ __forceinline__ uint32_t pack_h2(float a, float b) {
    __half2 h = __floats2half2_rn(a, b);
    return *(uint32_t*)&h;
}
__device__ __forceinline__ float fast_exp(float x) {
    float t = x * 1.4426950408889634f;
    int ii = __float2int_rn(t);
    float f = t - (float)ii;
    float y = f * 0.6931471805599453f;
    float p = 1.0f + y * (1.0f + y * (0.5f + y * (0.16666667f + y * (0.041666668f + y * 0.008333334f))));
    return __int_as_float(__float_as_int(p) + (ii << 23));
}
__device__ __forceinline__ void cp_async16(uint32_t smem_addr, const void* gptr) {
    asm volatile("cp.async.cg.shared.global [%0], [%1], 16;" :: "r"(smem_addr), "l"(gptr));
}
#define CP_COMMIT() asm volatile("cp.async.commit_group;" ::: "memory")
#define CP_WAIT(n)  asm volatile("cp.async.wait_group %0;" :: "n"(n) : "memory")

// ---------------------------------------------------------------------------
// Weight transpose to fp16 + zero g_sums (runs every replay)
// ---------------------------------------------------------------------------
__global__ __launch_bounds__(256) void convw_kernel(
    const float* __restrict__ Wq, const float* __restrict__ Wk, const float* __restrict__ Wv)
{
    __shared__ float sW[64 * 129];
    int w = blockIdx.x >> 4;
    int k0 = (blockIdx.x & 15) * 64;
    const float* W = (w == 0) ? Wq : (w == 1) ? Wk : Wv;
    int tid = threadIdx.x;

    for (int i = blockIdx.x * 256 + tid; i < NB * NS; i += gridDim.x * 256)
        g_sums[i] = 0.f;

    #pragma unroll
    for (int it = 0; it < 32; it++) {
        int f = tid + it * 256;
        int kk = f >> 7, n = f & 127;
        sW[kk * 129 + n] = W[(size_t)(k0 + kk) * ND + n];
    }
    __syncthreads();

    #pragma unroll
    for (int it = 0; it < 32; it++) {
        int f = tid + it * 256;
        int n = f >> 6, kk = f & 63;
        g_wt[(size_t)w * ND * NH + (size_t)n * NH + k0 + kk] =
            __float2half_rn(sW[kk * 129 + n]);
    }
}

// ---------------------------------------------------------------------------
// QKV GEMM: BM=128 BN=128 BK=32, 128 threads (4 warps 2x2, warp 64x64).
// 3-stage cp.async pipeline (prefetch distance 2).
// ---------------------------------------------------------------------------
#define FSTRIDE 36
#define BSTRIDE 40
#define QK_A   0                             // 128 x 36 fp32 = 18432 B
#define QK_B   18432                         // 128 x 40 fp16 = 10240 B
#define QK_STAGE 28672
#define QK_SMEM (3 * QK_STAGE)

__global__ __launch_bounds__(128, 2) void qkv_mma_kernel(
    const float* __restrict__ X,
    const float* __restrict__ bq, const float* __restrict__ bk, const float* __restrict__ bv)
{
    extern __shared__ char sm[];
    const uint32_t uS = smem_u32(sm);

    const int tid = threadIdx.x;
    const int wid = tid >> 5, lid = tid & 31;
    const int w  = blockIdx.x;
    const int m0 = blockIdx.y * 128;

    const __half* Wt = g_wt + (size_t)w * ND * NH;
    const float* bias = (w == 0) ? bq : (w == 1) ? bk : bv;
    __half* out = (w == 0) ? g_q : (w == 1) ? g_k : g_v;
    const float oscale = (w == 0) ? 0.08838834764831845f : 1.0f;

    const int warpM = (wid >> 1) * 64;
    const int warpN = (wid & 1) * 64;

    const int bx_row  = (lid & 7) + (lid >> 4) * 8;
    const int bx_koff = ((lid >> 3) & 1) * 8;
    const int p_row = lid >> 2;
    const int p_col = (lid & 3) * 2;

    float acc[4][8][4];
    #pragma unroll
    for (int i = 0; i < 4; i++)
        #pragma unroll
        for (int j = 0; j < 8; j++)
            #pragma unroll
            for (int c = 0; c < 4; c++) acc[i][j][c] = 0.f;

    auto issue_stage = [&](int kc, int s) {
        const int k0 = kc * 32;
        const uint32_t base = uS + s * QK_STAGE;
        #pragma unroll
        for (int it = 0; it < 8; it++) {
            int f = tid + it * 128;
            int row = f >> 3, u = f & 7;
            const float* src = X + (size_t)(m0 + row) * NH + k0 + u * 4;
            cp_async16(base + QK_A + (uint32_t)(row * FSTRIDE + u * 4) * 4, src);
        }
        #pragma unroll
        for (int it = 0; it < 4; it++) {
            int f = tid + it * 128;
            int row = f >> 2, u = f & 3;
            const __half* src = Wt + (size_t)row * NH + k0 + u * 8;
            cp_async16(base + QK_B + (uint32_t)(row * BSTRIDE + u * 8) * 2, src);
        }
        CP_COMMIT();
    };

    int sidx = 0;                      // stage slot of chunk kc
    issue_stage(0, 0);
    issue_stage(1, 1);

    for (int kc = 0; kc < 32; kc++) {
        if (kc < 30) { issue_stage(kc + 2, (kc + 2) % 3); CP_WAIT(2); }
        else if (kc == 30) { CP_WAIT(1); }
        else { CP_WAIT(0); }
        __syncthreads();

        const float* Ab = (const float*)(sm + sidx * QK_STAGE + QK_A);
        const uint32_t bb = uS + sidx * QK_STAGE;
        sidx = (sidx + 1) % 3;

        #pragma unroll
        for (int ks = 0; ks < 2; ks++) {
            uint32_t ah[4][4];
            #pragma unroll
            for (int mi = 0; mi < 4; mi++) {
                int row  = warpM + mi * 16 + p_row;
                int kcol = ks * 16 + p_col;
                float2 p0 = *(const float2*)&Ab[row * FSTRIDE + kcol];
                float2 p1 = *(const float2*)&Ab[(row + 8) * FSTRIDE + kcol];
                float2 p2 = *(const float2*)&Ab[row * FSTRIDE + kcol + 8];
                float2 p3 = *(const float2*)&Ab[(row + 8) * FSTRIDE + kcol + 8];
                ah[mi][0] = pack_h2(p0.x, p0.y);
                ah[mi][1] = pack_h2(p1.x, p1.y);
                ah[mi][2] = pack_h2(p2.x, p2.y);
                ah[mi][3] = pack_h2(p3.x, p3.y);
            }
            #pragma unroll
            for (int njp = 0; njp < 4; njp++) {
                uint32_t boff = ((warpN + njp * 16 + bx_row) * BSTRIDE + ks * 16 + bx_koff) * 2;
                uint32_t bh[4];
                ldsm_x4(bh, bb + QK_B + boff);
                #pragma unroll
                for (int h = 0; h < 2; h++)
                    #pragma unroll
                    for (int mi = 0; mi < 4; mi++)
                        mma16816(acc[mi][njp * 2 + h], ah[mi], &bh[h * 2]);
            }
        }
        __syncthreads();
    }

    #pragma unroll
    for (int mi = 0; mi < 4; mi++) {
        #pragma unroll
        for (int nj = 0; nj < 8; nj++) {
            int r0 = m0 + warpM + mi * 16 + (lid >> 2);
            int c0 = warpN + nj * 8 + (lid & 3) * 2;
            float b0 = bias[c0], b1 = bias[c0 + 1];
            uint32_t h01 = pack_h2((acc[mi][nj][0] + b0) * oscale, (acc[mi][nj][1] + b1) * oscale);
            uint32_t h23 = pack_h2((acc[mi][nj][2] + b0) * oscale, (acc[mi][nj][3] + b1) * oscale);
            *(uint32_t*)&out[(size_t)r0 * ND + c0] = h01;
            *(uint32_t*)&out[(size_t)(r0 + 8) * ND + c0] = h23;
        }
    }
}

// ---------------------------------------------------------------------------
// score_kernel: writes exp(S) fp16 (unnormalized) + atomic per-row exp-sums.
// 128 threads, 4 warps 2x2, warp 64x64. 2-stage pipeline (only 4 chunks).
// ---------------------------------------------------------------------------
#define SC_Q 0
#define SC_K 10240
#define SC_STAGE 20480
#define SC_SMEM (2 * SC_STAGE)

__global__ __launch_bounds__(128, 2) void score_kernel()
{
    extern __shared__ char sm[];
    const uint32_t uS = smem_u32(sm);

    const int tid = threadIdx.x;
    const int wid = tid >> 5, lid = tid & 31;
    const int m0 = blockIdx.x * 128;
    const int n0 = blockIdx.y * 128;
    const int b  = blockIdx.z;
    const size_t qbase = (size_t)(b * NS + m0) * ND;
    const size_t kbase = (size_t)(b * NS + n0) * ND;

    const int warpM = (wid >> 1) * 64;
    const int warpN = (wid & 1) * 64;
    const int a_row  = lid & 15;
    const int a_koff = (lid >> 4) * 8;
    const int bx_row  = (lid & 7) + (lid >> 4) * 8;
    const int bx_koff = ((lid >> 3) & 1) * 8;

    float acc[4][8][4];
    #pragma unroll
    for (int i = 0; i < 4; i++)
        #pragma unroll
        for (int j = 0; j < 8; j++)
            #pragma unroll
            for (int c = 0; c < 4; c++) acc[i][j][c] = 0.f;

    auto issue_stage = [&](int kc, int s) {
        const int k0 = kc * 32;
        const uint32_t base = uS + s * SC_STAGE;
        #pragma unroll
        for (int it = 0; it < 8; it++) {
            int f = tid + it * 128;
            int arr = f >> 9;
            int g = f & 511;
            int row = g >> 2, u = g & 3;
            const __half* src = (arr ? g_k + kbase : g_q + qbase) + (size_t)row * ND + k0 + u * 8;
            cp_async16(base + (arr ? SC_K : SC_Q) + (uint32_t)(row * BSTRIDE + u * 8) * 2, src);
        }
        CP_COMMIT();
    };

    issue_stage(0, 0);

    for (int kc = 0; kc < 4; kc++) {
        if (kc < 3) { issue_stage(kc + 1, (kc + 1) & 1); CP_WAIT(1); }
        else        { CP_WAIT(0); }
        __syncthreads();

        const uint32_t base = uS + (kc & 1) * SC_STAGE;
        #pragma unroll
        for (int ks = 0; ks < 2; ks++) {
            uint32_t ah[4][4];
            #pragma unroll
            for (int mi = 0; mi < 4; mi++) {
                uint32_t off = ((warpM + mi * 16 + a_row) * BSTRIDE + ks * 16 + a_koff) * 2;
                ldsm_x4(ah[mi], base + SC_Q + off);
            }
            #pragma unroll
            for (int njp = 0; njp < 4; njp++) {
                uint32_t boff = ((warpN + njp * 16 + bx_row) * BSTRIDE + ks * 16 + bx_koff) * 2;
                uint32_t bh[4];
                ldsm_x4(bh, base + SC_K + boff);
                #pragma unroll
                for (int h = 0; h < 2; h++)
                    #pragma unroll
                    for (int mi = 0; mi < 4; mi++)
                        mma16816(acc[mi][njp * 2 + h], ah[mi], &bh[h * 2]);
            }
        }
        __syncthreads();
    }

    // epilogue: exp -> fp16 scratch + row sums (shfl + atomic)
    __half* pe = g_pe + (size_t)b * NS * NS;
    #pragma unroll
    for (int mi = 0; mi < 4; mi++) {
        int r0 = m0 + warpM + mi * 16 + (lid >> 2);
        float rs0 = 0.f, rs1 = 0.f;
        #pragma unroll
        for (int nj = 0; nj < 8; nj++) {
            int c0 = n0 + warpN + nj * 8 + (lid & 3) * 2;
            float e0 = fast_exp(acc[mi][nj][0]);
            float e1 = fast_exp(acc[mi][nj][1]);
            float e2 = fast_exp(acc[mi][nj][2]);
            float e3 = fast_exp(acc[mi][nj][3]);
            *(uint32_t*)&pe[(size_t)r0 * NS + c0]       = pack_h2(e0, e1);
            *(uint32_t*)&pe[(size_t)(r0 + 8) * NS + c0] = pack_h2(e2, e3);
            rs0 += e0 + e1;
            rs1 += e2 + e3;
        }
        rs0 += __shfl_xor_sync(0xffffffffu, rs0, 1);
        rs0 += __shfl_xor_sync(0xffffffffu, rs0, 2);
        rs1 += __shfl_xor_sync(0xffffffffu, rs1, 1);
        rs1 += __shfl_xor_sync(0xffffffffu, rs1, 2);
        if ((lid & 3) == 0) {
            atomicAdd(&g_sums[b * NS + r0], rs0);
            atomicAdd(&g_sums[b * NS + r0 + 8], rs1);
        }
    }
}

// ---------------------------------------------------------------------------
// pv_kernel: O = (expS_fp16 @ V) * inv_sum; writes normalized fp32 probs
// in-mainloop from staged P (R14 structure). 3-stage cp.async pipeline.
// BM=64, grid(16,32)=512, 128 threads (4 warps 2x2, warp 32x64), 4 CTAs/SM.
// ---------------------------------------------------------------------------
#define PV_P   0                             // 64 x 40 fp16 = 5120 B
#define PV_V   5120                          // 32 x 136 fp16 = 8704 B
#define PV_STAGE 13824
#define PV_SMEM (3 * PV_STAGE)
#define VSTRIDE 136

__global__ __launch_bounds__(128, 4) void pv_kernel(float* __restrict__ probs,
                                                    float* __restrict__ o_out)
{
    extern __shared__ char sm[];
    __shared__ float s_inv[64];
    const uint32_t uS = smem_u32(sm);

    const int tid = threadIdx.x;
    const int wid = tid >> 5, lid = tid & 31;
    const int m0 = blockIdx.x * 64;
    const int b  = blockIdx.y;
    const size_t pbase = (size_t)(b * NS + m0) * NS;
    const size_t vbase = (size_t)(b * NS) * ND;

    const int warpM = (wid >> 1) * 32;       // 0, 32
    const int warpN = (wid & 1) * 64;        // 0, 64
    const int a_row  = lid & 15;
    const int a_koff = (lid >> 4) * 8;
    const int t_krow = (lid & 7) + ((lid >> 3) & 1) * 8;
    const int t_ncol = (lid >> 4) * 8;
    const int p_row = lid >> 2;

    if (tid < 64) s_inv[tid] = 1.0f / g_sums[b * NS + m0 + tid];

    float acc[2][8][4];
    #pragma unroll
    for (int i = 0; i < 2; i++)
        #pragma unroll
        for (int j = 0; j < 8; j++)
            #pragma unroll
            for (int c = 0; c < 4; c++) acc[i][j][c] = 0.f;

    auto issue_stage = [&](int kc, int s) {
        const int k0 = kc * 32;
        const uint32_t base = uS + s * PV_STAGE;
        // P: 64 rows x 32 fp16 = 256 cp16
        #pragma unroll
        for (int it = 0; it < 2; it++) {
            int f = tid + it * 128;
            int row = f >> 2, u = f & 3;
            const __half* src = g_pe + pbase + (size_t)row * NS + k0 + u * 8;
            cp_async16(base + PV_P + (uint32_t)(row * BSTRIDE + u * 8) * 2, src);
        }
        // V: 32 rows x 128 fp16 = 512 cp16
        #pragma unroll
        for (int it = 0; it < 4; it++) {
            int f = tid + it * 128;
            int row = f >> 4, u = f & 15;
            const __half* src = g_v + vbase + (size_t)(k0 + row) * ND + u * 8;
            cp_async16(base + PV_V + (uint32_t)(row * VSTRIDE + u * 8) * 2, src);
        }
        CP_COMMIT();
    };

    issue_stage(0, 0);
    issue_stage(1, 1);
    __syncthreads();   // s_inv visible

    float inv0[2], inv1[2];
    #pragma unroll
    for (int mi = 0; mi < 2; mi++) {
        inv0[mi] = s_inv[warpM + mi * 16 + p_row];
        inv1[mi] = s_inv[warpM + mi * 16 + p_row + 8];
    }

    int sidx = 0;
    for (int kc = 0; kc < 32; kc++) {
        if (kc < 30) { issue_stage(kc + 2, (kc + 2) % 3); CP_WAIT(2); }
        else if (kc == 30) { CP_WAIT(1); }
        else { CP_WAIT(0); }
        __syncthreads();

        const uint32_t pb = uS + sidx * PV_STAGE;
        const char* stg = sm + sidx * PV_STAGE;
        sidx = (sidx + 1) % 3;
        const int k0c = kc * 32;

        #pragma unroll
        for (int ks = 0; ks < 2; ks++) {
            uint32_t ph[2][4];
            #pragma unroll
            for (int mi = 0; mi < 2; mi++) {
                uint32_t off = ((warpM + mi * 16 + a_row) * BSTRIDE + ks * 16 + a_koff) * 2;
                ldsm_x4(ph[mi], pb + PV_P + off);
            }
            #pragma unroll
            for (int njp = 0; njp < 4; njp++) {
                uint32_t toff = (uint32_t)((ks * 16 + t_krow) * VSTRIDE + warpN + njp * 16 + t_ncol) * 2;
                uint32_t vh[4];
                ldsm_x4_t(vh, pb + PV_V + toff);
                #pragma unroll
                for (int h = 0; h < 2; h++)
                    #pragma unroll
                    for (int mi = 0; mi < 2; mi++)
                        mma16816(acc[mi][njp * 2 + h], ph[mi], &vh[h * 2]);
            }
        }

        // write normalized fp32 probs chunk (from staged fp16 expS)
        #pragma unroll
        for (int it = 0; it < 2; it++) {
            int f = tid + it * 128;
            int row = f >> 2, u = f & 3;
            uint4 raw = *(const uint4*)(stg + PV_P + (uint32_t)(row * BSTRIDE + u * 8) * 2);
            float iv = s_inv[row];
            float2 a0 = __half22float2(*(__half2*)&raw.x);
            float2 a1 = __half22float2(*(__half2*)&raw.y);
            float2 a2 = __half22float2(*(__half2*)&raw.z);
            float2 a3 = __half22float2(*(__half2*)&raw.w);
            float4 o0 = make_float4(a0.x * iv, a0.y * iv, a1.x * iv, a1.y * iv);
            float4 o1 = make_float4(a2.x * iv, a2.y * iv, a3.x * iv, a3.y * iv);
            *(float4*)&probs[pbase + (size_t)row * NS + k0c + u * 8]     = o0;
            *(float4*)&probs[pbase + (size_t)row * NS + k0c + u * 8 + 4] = o1;
        }
        __syncthreads();
    }

    #pragma unroll
    for (int mi = 0; mi < 2; mi++) {
        #pragma unroll
        for (int nj = 0; nj < 8; nj++) {
            int r0 = m0 + warpM + mi * 16 + (lid >> 2);
            int c0 = warpN + nj * 8 + (lid & 3) * 2;
            *(float2*)&o_out[((size_t)(b * NS) + r0) * ND + c0] =
                make_float2(acc[mi][nj][0] * inv0[mi], acc[mi][nj][1] * inv0[mi]);
            *(float2*)&o_out[((size_t)(b * NS) + r0 + 8) * ND + c0] =
                make_float2(acc[mi][nj][2] * inv1[mi], acc[mi][nj][3] * inv1[mi]);
        }
    }
}

// ---------------------------------------------------------------------------
extern "C" void kernel_launch(void* const* d_in, const int* in_sizes, int n_in,
                              void* d_out, int out_size)
{
    const float* X  = (const float*)d_in[0];
    const float* Wq = (const float*)d_in[1];
    const float* bq = (const float*)d_in[2];
    const float* Wk = (const float*)d_in[3];
    const float* bk = (const float*)d_in[4];
    const float* Wv = (const float*)d_in[5];
    const float* bv = (const float*)d_in[6];

    float* out   = (float*)d_out;                 // [32,1024,128]
    float* probs = out + (size_t)NB * NS * ND;    // [32,1024,1024]

    cudaFuncSetAttribute(qkv_mma_kernel, cudaFuncAttributeMaxDynamicSharedMemorySize, QK_SMEM);
    cudaFuncSetAttribute(score_kernel, cudaFuncAttributeMaxDynamicSharedMemorySize, SC_SMEM);
    cudaFuncSetAttribute(pv_kernel, cudaFuncAttributeMaxDynamicSharedMemorySize, PV_SMEM);

    convw_kernel<<<48, 256>>>(Wq, Wk, Wv);
    qkv_mma_kernel<<<dim3(3, 256), 128, QK_SMEM>>>(X, bq, bk, bv);
    score_kernel<<<dim3(8, 8, 32), 128, SC_SMEM>>>();
    pv_kernel<<<dim3(16, 32), 128, PV_SMEM>>>(probs, out);
}